// round 1
// baseline (speedup 1.0000x reference)
#include <cuda_runtime.h>

#define CH 128
#define NB 8
#define SP 16384              // spatial = 128*128
#define BSTRIDE (CH*SP)
#define GROUPS 8
#define GSIZE 16
#define HEADS 8
#define HD 16
#define EPS 1e-5f

// -------- device scratch (no allocs allowed) --------
__device__ float g_S[NB][CH][CH];     // per-batch X X^T
__device__ float g_r[NB][CH];         // per-batch row sums of X
__device__ float g_alpha[NB][CH];
__device__ float g_Bp[NB][CH];        // B' (effective bias after GN+conv_in)
__device__ float g_u[NB][CH];         // W' r
__device__ float g_M[NB][CH][CH];     // conv_out composed with softmax weights
__device__ float g_Ct[NB][CH][CH];    // C transposed: g_Ct[b][c][o] = C[o][c]
__device__ float g_d[NB][CH];

// -------- zero scratch (graph replays reuse globals) --------
__global__ void k_zero() {
    int idx = blockIdx.x * blockDim.x + threadIdx.x;
    if (idx < NB*CH*CH) ((float*)g_S)[idx] = 0.f;
    if (idx < NB*CH)    ((float*)g_r)[idx] = 0.f;
}

// -------- kernel 1: per-batch syrk S = X X^T (upper tiles) + row sums --------
// grid (3 tiles, 16 s-splits, 8 batches), 256 threads
__global__ __launch_bounds__(256) void k_syrk(const float* __restrict__ x) {
    int b = blockIdx.z;
    int tile = blockIdx.x;            // 0:(0,0) 1:(0,1) 2:(1,1) in 64x64 tiles
    int ti = (tile == 2) ? 1 : 0;
    int tj = (tile == 0) ? 0 : 1;
    int arow0 = ti * 64, brow0 = tj * 64;
    int s0 = blockIdx.y * 1024;
    bool diag = (ti == tj);

    __shared__ __align__(16) float As[16][68];
    __shared__ __align__(16) float Bs[16][68];

    int t = threadIdx.x;
    int r = t >> 2, q = t & 3;        // loader role: row r (0..63), quad q
    int tx = t & 15, ty = t >> 4;     // compute role: 4x4 of 64x64 tile

    float acc[4][4];
    #pragma unroll
    for (int i = 0; i < 4; ++i)
        #pragma unroll
        for (int j = 0; j < 4; ++j) acc[i][j] = 0.f;
    float rsum = 0.f;

    const float* xb = x + (size_t)b * BSTRIDE;
    const float* pa = xb + (arow0 + r) * SP + s0 + 4 * q;
    const float* pb = xb + (brow0 + r) * SP + s0 + 4 * q;

    for (int ch = 0; ch < 64; ++ch) {
        float4 av = *(const float4*)(pa + ch * 16);
        float4 bv = *(const float4*)(pb + ch * 16);
        __syncthreads();
        As[4*q+0][r] = av.x; As[4*q+1][r] = av.y; As[4*q+2][r] = av.z; As[4*q+3][r] = av.w;
        Bs[4*q+0][r] = bv.x; Bs[4*q+1][r] = bv.y; Bs[4*q+2][r] = bv.z; Bs[4*q+3][r] = bv.w;
        if (diag) rsum += av.x + av.y + av.z + av.w;
        __syncthreads();
        #pragma unroll
        for (int k = 0; k < 16; ++k) {
            float4 a  = *(const float4*)&As[k][4*ty];
            float4 bb = *(const float4*)&Bs[k][4*tx];
            float aa[4] = {a.x, a.y, a.z, a.w};
            float bbv[4] = {bb.x, bb.y, bb.z, bb.w};
            #pragma unroll
            for (int i = 0; i < 4; ++i)
                #pragma unroll
                for (int j = 0; j < 4; ++j)
                    acc[i][j] += aa[i] * bbv[j];
        }
    }
    #pragma unroll
    for (int i = 0; i < 4; ++i)
        #pragma unroll
        for (int j = 0; j < 4; ++j)
            atomicAdd(&g_S[b][arow0 + 4*ty + i][brow0 + 4*tx + j], acc[i][j]);
    if (diag) atomicAdd(&g_r[b][arow0 + r], rsum);
}

// -------- prep1: GN stats from S diag + r, alpha/beta, B', u, mirror S --------
// grid 8 batches, 128 threads
__global__ __launch_bounds__(128) void k_prep1(const float* __restrict__ gn_w,
                                               const float* __restrict__ gn_b,
                                               const float* __restrict__ w_in,
                                               const float* __restrict__ b_in) {
    int b = blockIdx.x;
    int t = threadIdx.x;   // channel
    __shared__ float r_s[CH], sq_s[CH], alpha_s[CH], beta_s[CH];
    r_s[t]  = g_r[b][t];
    sq_s[t] = g_S[b][t][t];
    __syncthreads();
    int g0 = (t >> 4) << 4;
    float sum = 0.f, sumsq = 0.f;
    #pragma unroll
    for (int i = 0; i < GSIZE; ++i) { sum += r_s[g0 + i]; sumsq += sq_s[g0 + i]; }
    const float inv_cnt = 1.f / (float)(GSIZE * SP);
    float mu  = sum * inv_cnt;
    float var = sumsq * inv_cnt - mu * mu;
    float al = gn_w[t] * rsqrtf(var + EPS);
    float be = gn_b[t] - mu * al;
    alpha_s[t] = al; beta_s[t] = be;
    g_alpha[b][t] = al;
    __syncthreads();
    // B'[o] and u[o] = (W' r)[o]
    float bp = b_in[t], uu = 0.f;
    const float* wrow = w_in + t * CH;
    for (int c = 0; c < CH; ++c) {
        float w = wrow[c];
        bp += w * beta_s[c];
        uu += w * alpha_s[c] * r_s[c];
    }
    g_Bp[b][t] = bp;
    g_u[b][t]  = uu;
    // mirror S lower-left from upper-right
    for (int idx = t; idx < 64 * 64; idx += 128) {
        int i = idx >> 6, j = idx & 63;
        g_S[b][64 + i][j] = g_S[b][j][64 + i];
    }
}

// -------- prep2: per (b,h) Gram block -> softmax -> M column block --------
// grid 64 (b*8+h), 128 threads
__global__ __launch_bounds__(128) void k_prep2(const float* __restrict__ w_in,
                                               const float* __restrict__ w_out) {
    int b = blockIdx.x >> 3, h = blockIdx.x & 7;
    int t = threadIdx.x;
    __shared__ float Whs[16][CH];
    __shared__ float Ts[16][CH];
    __shared__ float sc[16][17];
    __shared__ float Wt[16][17];

    for (int idx = t; idx < 16 * CH; idx += 128) {
        int i = idx >> 7, k = idx & 127;
        Whs[i][k] = w_in[(h * 16 + i) * CH + k] * g_alpha[b][k];
    }
    __syncthreads();
    // T = Wh * S ; thread t handles column l = t
    {
        float ta[16];
        #pragma unroll
        for (int i = 0; i < 16; ++i) ta[i] = 0.f;
        for (int k = 0; k < CH; ++k) {
            float sv = g_S[b][k][t];
            #pragma unroll
            for (int i = 0; i < 16; ++i) ta[i] += Whs[i][k] * sv;
        }
        #pragma unroll
        for (int i = 0; i < 16; ++i) Ts[i][t] = ta[i];
    }
    __syncthreads();
    // Gram entries + rank-1 terms; thread does (i, j0) and (i, j0+8)
    {
        int i = t >> 3, j0 = t & 7;
        float g0v = 0.f, g1v = 0.f;
        for (int l = 0; l < CH; ++l) {
            float tv = Ts[i][l];
            g0v += tv * Whs[j0][l];
            g1v += tv * Whs[j0 + 8][l];
        }
        float ui  = g_u[b][h*16 + i],      bi  = g_Bp[b][h*16 + i];
        float uj0 = g_u[b][h*16 + j0],     bj0 = g_Bp[b][h*16 + j0];
        float uj1 = g_u[b][h*16 + j0 + 8], bj1 = g_Bp[b][h*16 + j0 + 8];
        sc[i][j0]     = 0.25f * (g0v + ui*bj0 + bi*uj0 + (float)SP * bi * bj0);
        sc[i][j0 + 8] = 0.25f * (g1v + ui*bj1 + bi*uj1 + (float)SP * bi * bj1);
    }
    __syncthreads();
    if (t < 16) {
        float m = sc[t][0];
        #pragma unroll
        for (int j = 1; j < 16; ++j) m = fmaxf(m, sc[t][j]);
        float e[16], s = 0.f;
        #pragma unroll
        for (int j = 0; j < 16; ++j) { e[j] = expf(sc[t][j] - m); s += e[j]; }
        float inv = 1.f / s;
        #pragma unroll
        for (int j = 0; j < 16; ++j) Wt[t][j] = e[j] * inv;
    }
    __syncthreads();
    // M[o][h*16+j] = sum_i w_out[o][h*16+i] * Wt[i][j] ; thread = o
    {
        float wo[16];
        #pragma unroll
        for (int i = 0; i < 16; ++i) wo[i] = w_out[t * CH + h * 16 + i];
        #pragma unroll
        for (int j = 0; j < 16; ++j) {
            float m = 0.f;
            #pragma unroll
            for (int i = 0; i < 16; ++i) m += wo[i] * Wt[i][j];
            g_M[b][t][h * 16 + j] = m;
        }
    }
}

// -------- prep3: C^T = (M W')^T stored [c][o], and d = M B' + b_out --------
// grid (8 o-tiles, 8 batches), 128 threads (thread = column c)
__global__ __launch_bounds__(128) void k_prep3(const float* __restrict__ w_in,
                                               const float* __restrict__ b_out) {
    int b = blockIdx.y, o0 = blockIdx.x * 16;
    int t = threadIdx.x;  // = c
    __shared__ float Ms[16][CH];
    __shared__ float Bp_s[CH];
    for (int idx = t; idx < 16 * CH; idx += 128) {
        int i = idx >> 7, k = idx & 127;
        Ms[i][k] = g_M[b][o0 + i][k];
    }
    Bp_s[t] = g_Bp[b][t];
    __syncthreads();
    float a[16];
    #pragma unroll
    for (int i = 0; i < 16; ++i) a[i] = 0.f;
    for (int k = 0; k < CH; ++k) {
        float wv = w_in[k * CH + t];
        #pragma unroll
        for (int i = 0; i < 16; ++i) a[i] += Ms[i][k] * wv;
    }
    float al = g_alpha[b][t];
    #pragma unroll
    for (int i = 0; i < 16; ++i) g_Ct[b][t][o0 + i] = al * a[i];
    if (t < 16) {
        float dv = b_out[o0 + t];
        for (int k = 0; k < CH; ++k) dv += Ms[t][k] * Bp_s[k];
        g_d[b][o0 + t] = dv;
    }
}

// -------- main: out = x + C x + d  (per-batch 128x16384x128 GEMM) --------
// grid (256 s-tiles of 64, 8 batches), 256 threads, dynamic smem ~96.5KB
#define SMEM_MAIN ((CH*CH + CH*64 + CH) * 4)
__global__ __launch_bounds__(256) void k_main(const float* __restrict__ x,
                                              float* __restrict__ out) {
    extern __shared__ float smem[];
    float* Cts = smem;                 // [128][128], Cts[c][o]
    float* xs  = smem + CH * CH;       // [128][64]
    float* d_s = xs + CH * 64;         // [128]

    int b = blockIdx.y;
    int s0 = blockIdx.x * 64;
    int t = threadIdx.x;

    const float4* Ct4 = (const float4*)&g_Ct[b][0][0];
    float4* Cts4 = (float4*)Cts;
    for (int idx = t; idx < CH * CH / 4; idx += 256) Cts4[idx] = Ct4[idx];

    const float* xb = x + (size_t)b * BSTRIDE + s0;
    float4* xs4 = (float4*)xs;
    for (int idx = t; idx < CH * 16; idx += 256) {
        int row = idx >> 4, c4 = idx & 15;
        xs4[row * 16 + c4] = *(const float4*)(xb + row * SP + c4 * 4);
    }
    if (t < CH) d_s[t] = g_d[b][t];
    __syncthreads();

    int sx = t & 15, oy = t >> 4;       // 4 spatial cols, 8 output rows
    float acc[8][4];
    #pragma unroll
    for (int i = 0; i < 8; ++i)
        #pragma unroll
        for (int j = 0; j < 4; ++j) acc[i][j] = 0.f;

    for (int c = 0; c < CH; ++c) {
        float4 xv = xs4[c * 16 + sx];
        float4 a0 = Cts4[c * 32 + oy * 2];
        float4 a1 = Cts4[c * 32 + oy * 2 + 1];
        float av[8]  = {a0.x, a0.y, a0.z, a0.w, a1.x, a1.y, a1.z, a1.w};
        float xvv[4] = {xv.x, xv.y, xv.z, xv.w};
        #pragma unroll
        for (int rr = 0; rr < 8; ++rr)
            #pragma unroll
            for (int q = 0; q < 4; ++q)
                acc[rr][q] += av[rr] * xvv[q];
    }

    float* ob = out + (size_t)b * BSTRIDE + s0;
    #pragma unroll
    for (int rr = 0; rr < 8; ++rr) {
        int ro = oy * 8 + rr;
        float dd = d_s[ro];
        float4 xv = xs4[ro * 16 + sx];
        float4 o;
        o.x = xv.x + acc[rr][0] + dd;
        o.y = xv.y + acc[rr][1] + dd;
        o.z = xv.z + acc[rr][2] + dd;
        o.w = xv.w + acc[rr][3] + dd;
        *(float4*)(ob + ro * SP + sx * 4) = o;
    }
}

extern "C" void kernel_launch(void* const* d_in, const int* in_sizes, int n_in,
                              void* d_out, int out_size) {
    const float* x    = (const float*)d_in[0];
    const float* gn_w = (const float*)d_in[1];
    const float* gn_b = (const float*)d_in[2];
    const float* w_in = (const float*)d_in[3];
    const float* b_in = (const float*)d_in[4];
    const float* w_out= (const float*)d_in[5];
    const float* b_out= (const float*)d_in[6];
    float* out = (float*)d_out;
    (void)in_sizes; (void)n_in; (void)out_size;

    cudaFuncSetAttribute(k_main, cudaFuncAttributeMaxDynamicSharedMemorySize, SMEM_MAIN);

    k_zero<<<512, 256>>>();
    dim3 gs(3, 16, NB);
    k_syrk<<<gs, 256>>>(x);
    k_prep1<<<NB, 128>>>(gn_w, gn_b, w_in, b_in);
    k_prep2<<<64, 128>>>(w_in, w_out);
    k_prep3<<<dim3(8, NB), 128>>>(w_in, b_out);
    k_main<<<dim3(SP / 64, NB), 256, SMEM_MAIN>>>(x, out);
}

// round 3
// speedup vs baseline: 1.1136x; 1.1136x over previous
#include <cuda_runtime.h>

#define CH 128
#define NB 8
#define SP 16384              // spatial = 128*128
#define BSTRIDE (CH*SP)
#define GROUPS 8
#define GSIZE 16
#define HEADS 8
#define HD 16
#define EPS 1e-5f

typedef unsigned long long u64;

// packed fp32x2 helpers (Blackwell f32x2 pipe: 2 MACs per fma slot)
__device__ __forceinline__ u64 pack2(float lo, float hi) {
    u64 r; asm("mov.b64 %0, {%1,%2};" : "=l"(r) : "f"(lo), "f"(hi)); return r;
}
__device__ __forceinline__ void fma2(u64& d, u64 a, u64 b) {
    asm("fma.rn.f32x2 %0, %1, %2, %0;" : "+l"(d) : "l"(a), "l"(b));
}
__device__ __forceinline__ float2 unpack2(u64 v) {
    float2 f; asm("mov.b64 {%0,%1}, %2;" : "=f"(f.x), "=f"(f.y) : "l"(v)); return f;
}

// -------- device scratch (no allocs allowed) --------
__device__ float g_S[NB][CH][CH];     // per-batch X X^T
__device__ float g_r[NB][CH];         // per-batch row sums of X
__device__ float g_alpha[NB][CH];
__device__ float g_Bp[NB][CH];        // B' (effective bias after GN+conv_in)
__device__ float g_u[NB][CH];         // W' r
__device__ float g_M[NB][CH][CH];     // conv_out composed with softmax weights
__device__ float g_Ct[NB][CH][CH];    // C transposed: g_Ct[b][c][o] = C[o][c]
__device__ float g_d[NB][CH];

// -------- zero scratch (graph replays reuse globals) --------
__global__ void k_zero() {
    int idx = blockIdx.x * blockDim.x + threadIdx.x;
    if (idx < NB*CH*CH) ((float*)g_S)[idx] = 0.f;
    if (idx < NB*CH)    ((float*)g_r)[idx] = 0.f;
}

// -------- kernel 1: per-batch syrk S = X X^T (upper tiles) + row sums --------
// grid (3 tiles, 16 s-splits, 8 batches), 256 threads
__global__ __launch_bounds__(256) void k_syrk(const float* __restrict__ x) {
    int b = blockIdx.z;
    int tile = blockIdx.x;            // 0:(0,0) 1:(0,1) 2:(1,1) in 64x64 tiles
    int ti = (tile == 2) ? 1 : 0;
    int tj = (tile == 0) ? 0 : 1;
    int arow0 = ti * 64, brow0 = tj * 64;
    int s0 = blockIdx.y * 1024;
    bool diag = (ti == tj);

    __shared__ __align__(16) float As[16][68];
    __shared__ __align__(16) float Bs[16][68];

    int t = threadIdx.x;
    int r = t >> 2, q = t & 3;        // loader role: row r (0..63), quad q
    int tx = t & 15, ty = t >> 4;     // compute role: 4x4 of 64x64 tile

    u64 acc2[4][2];
    #pragma unroll
    for (int i = 0; i < 4; ++i) { acc2[i][0] = 0ull; acc2[i][1] = 0ull; }
    float rsum = 0.f;

    const float* xb = x + (size_t)b * BSTRIDE;
    const float* pa = xb + (arow0 + r) * SP + s0 + 4 * q;
    const float* pb = xb + (brow0 + r) * SP + s0 + 4 * q;

    for (int ch = 0; ch < 64; ++ch) {
        float4 av = *(const float4*)(pa + ch * 16);
        float4 bv = *(const float4*)(pb + ch * 16);
        __syncthreads();
        As[4*q+0][r] = av.x; As[4*q+1][r] = av.y; As[4*q+2][r] = av.z; As[4*q+3][r] = av.w;
        Bs[4*q+0][r] = bv.x; Bs[4*q+1][r] = bv.y; Bs[4*q+2][r] = bv.z; Bs[4*q+3][r] = bv.w;
        if (diag) rsum += av.x + av.y + av.z + av.w;
        __syncthreads();
        #pragma unroll
        for (int k = 0; k < 16; ++k) {
            float4 a = *(const float4*)&As[k][4*ty];
            u64 b0 = *(const u64*)&Bs[k][4*tx];       // 16B-aligned rows (stride 272B)
            u64 b1 = *(const u64*)&Bs[k][4*tx + 2];
            float aa[4] = {a.x, a.y, a.z, a.w};
            #pragma unroll
            for (int i = 0; i < 4; ++i) {
                u64 ab = pack2(aa[i], aa[i]);
                fma2(acc2[i][0], ab, b0);
                fma2(acc2[i][1], ab, b1);
            }
        }
    }
    #pragma unroll
    for (int i = 0; i < 4; ++i) {
        float2 v0 = unpack2(acc2[i][0]);
        float2 v1 = unpack2(acc2[i][1]);
        atomicAdd(&g_S[b][arow0 + 4*ty + i][brow0 + 4*tx + 0], v0.x);
        atomicAdd(&g_S[b][arow0 + 4*ty + i][brow0 + 4*tx + 1], v0.y);
        atomicAdd(&g_S[b][arow0 + 4*ty + i][brow0 + 4*tx + 2], v1.x);
        atomicAdd(&g_S[b][arow0 + 4*ty + i][brow0 + 4*tx + 3], v1.y);
    }
    if (diag) atomicAdd(&g_r[b][arow0 + r], rsum);
}

// -------- prep1: GN stats from S diag + r, alpha/beta, B', u, mirror S --------
// grid 8 batches, 128 threads
__global__ __launch_bounds__(128) void k_prep1(const float* __restrict__ gn_w,
                                               const float* __restrict__ gn_b,
                                               const float* __restrict__ w_in,
                                               const float* __restrict__ b_in) {
    int b = blockIdx.x;
    int t = threadIdx.x;   // channel
    __shared__ float r_s[CH], sq_s[CH], alpha_s[CH], beta_s[CH];
    r_s[t]  = g_r[b][t];
    sq_s[t] = g_S[b][t][t];
    __syncthreads();
    int g0 = (t >> 4) << 4;
    float sum = 0.f, sumsq = 0.f;
    #pragma unroll
    for (int i = 0; i < GSIZE; ++i) { sum += r_s[g0 + i]; sumsq += sq_s[g0 + i]; }
    const float inv_cnt = 1.f / (float)(GSIZE * SP);
    float mu  = sum * inv_cnt;
    float var = sumsq * inv_cnt - mu * mu;
    float al = gn_w[t] * rsqrtf(var + EPS);
    float be = gn_b[t] - mu * al;
    alpha_s[t] = al; beta_s[t] = be;
    g_alpha[b][t] = al;
    __syncthreads();
    // B'[o] and u[o] = (W' r)[o]
    float bp = b_in[t], uu = 0.f;
    const float* wrow = w_in + t * CH;
    for (int c = 0; c < CH; ++c) {
        float w = wrow[c];
        bp += w * beta_s[c];
        uu += w * alpha_s[c] * r_s[c];
    }
    g_Bp[b][t] = bp;
    g_u[b][t]  = uu;
    // mirror S lower-left from upper-right
    for (int idx = t; idx < 64 * 64; idx += 128) {
        int i = idx >> 6, j = idx & 63;
        g_S[b][64 + i][j] = g_S[b][j][64 + i];
    }
}

// -------- prep2: per (b,h) Gram block -> softmax -> M column block --------
// grid 64 (b*8+h), 256 threads, S staged into dynamic smem
#define WSTR 129   // padded row stride to avoid 16-way bank conflicts
#define SMEM_P2 ((CH*CH + 2*16*WSTR + 2*16*17) * 4)
__global__ __launch_bounds__(256) void k_prep2(const float* __restrict__ w_in,
                                               const float* __restrict__ w_out) {
    extern __shared__ float sm2[];
    float* Ss  = sm2;                       // [128][128]
    float* Whs = Ss + CH * CH;              // [16][WSTR]
    float* Ts  = Whs + 16 * WSTR;           // [16][WSTR]
    float* sc  = Ts + 16 * WSTR;            // [16][17]
    float* Wt  = sc + 16 * 17;              // [16][17]

    int b = blockIdx.x >> 3, h = blockIdx.x & 7;
    int t = threadIdx.x;

    // stage S (coalesced float4)
    {
        const float4* src = (const float4*)&g_S[b][0][0];
        float4* dst = (float4*)Ss;
        for (int idx = t; idx < CH * CH / 4; idx += 256) dst[idx] = src[idx];
    }
    // Wh rows scaled by alpha
    for (int idx = t; idx < 16 * CH; idx += 256) {
        int i = idx >> 7, k = idx & 127;
        Whs[i * WSTR + k] = w_in[(h * 16 + i) * CH + k] * g_alpha[b][k];
    }
    __syncthreads();

    // T = Wh * S ; thread: column l = t&127, i-half = t>>7 (8 rows each)
    {
        int l = t & 127, ih = (t >> 7) * 8;
        float ta[8];
        #pragma unroll
        for (int i = 0; i < 8; ++i) ta[i] = 0.f;
        for (int k = 0; k < CH; ++k) {
            float sv = Ss[k * CH + l];
            #pragma unroll
            for (int i = 0; i < 8; ++i) ta[i] += Whs[(ih + i) * WSTR + k] * sv;
        }
        #pragma unroll
        for (int i = 0; i < 8; ++i) Ts[(ih + i) * WSTR + l] = ta[i];
    }
    __syncthreads();

    // Gram + rank-1 terms: thread = (i = t>>4, j = t&15)
    {
        int i = t >> 4, j = t & 15;
        float g = 0.f;
        for (int l = 0; l < CH; ++l)
            g += Ts[i * WSTR + l] * Whs[j * WSTR + l];
        float ui = g_u[b][h*16 + i], bi = g_Bp[b][h*16 + i];
        float uj = g_u[b][h*16 + j], bj = g_Bp[b][h*16 + j];
        sc[i * 17 + j] = 0.25f * (g + ui*bj + bi*uj + (float)SP * bi * bj);
    }
    __syncthreads();

    if (t < 16) {
        float m = sc[t * 17 + 0];
        #pragma unroll
        for (int j = 1; j < 16; ++j) m = fmaxf(m, sc[t * 17 + j]);
        float e[16], s = 0.f;
        #pragma unroll
        for (int j = 0; j < 16; ++j) { e[j] = expf(sc[t * 17 + j] - m); s += e[j]; }
        float inv = 1.f / s;
        #pragma unroll
        for (int j = 0; j < 16; ++j) Wt[t * 17 + j] = e[j] * inv;
    }
    __syncthreads();

    // M[o][h*16+j] = sum_i w_out[o][h*16+i] * Wt[i][j]; thread: o = t&127, j-half = t>>7
    {
        int o = t & 127, jh = (t >> 7) * 8;
        float wo[16];
        #pragma unroll
        for (int i = 0; i < 16; ++i) wo[i] = w_out[o * CH + h * 16 + i];
        #pragma unroll
        for (int j = 0; j < 8; ++j) {
            float m = 0.f;
            #pragma unroll
            for (int i = 0; i < 16; ++i) m += wo[i] * Wt[i * 17 + jh + j];
            g_M[b][o][h * 16 + jh + j] = m;
        }
    }
}

// -------- prep3: C^T = (M W')^T stored [c][o], and d = M B' + b_out --------
// grid (8 o-tiles, 8 batches), 128 threads (thread = column c)
__global__ __launch_bounds__(128) void k_prep3(const float* __restrict__ w_in,
                                               const float* __restrict__ b_out) {
    int b = blockIdx.y, o0 = blockIdx.x * 16;
    int t = threadIdx.x;  // = c
    __shared__ float Ms[16][CH];
    __shared__ float Bp_s[CH];
    for (int idx = t; idx < 16 * CH; idx += 128) {
        int i = idx >> 7, k = idx & 127;
        Ms[i][k] = g_M[b][o0 + i][k];
    }
    Bp_s[t] = g_Bp[b][t];
    __syncthreads();
    float a[16];
    #pragma unroll
    for (int i = 0; i < 16; ++i) a[i] = 0.f;
    for (int k = 0; k < CH; ++k) {
        float wv = w_in[k * CH + t];
        #pragma unroll
        for (int i = 0; i < 16; ++i) a[i] += Ms[i][k] * wv;
    }
    float al = g_alpha[b][t];
    #pragma unroll
    for (int i = 0; i < 16; ++i) g_Ct[b][t][o0 + i] = al * a[i];
    if (t < 16) {
        float dv = b_out[o0 + t];
        for (int k = 0; k < CH; ++k) dv += Ms[t][k] * Bp_s[k];
        g_d[b][o0 + t] = dv;
    }
}

// -------- main: out = x + C x + d  (per-batch 128x16384x128 GEMM) --------
// grid (256 s-tiles of 64, 8 batches), 256 threads, dynamic smem ~96.5KB
#define SMEM_MAIN ((CH*CH + CH*64 + CH) * 4)
__global__ __launch_bounds__(256) void k_main(const float* __restrict__ x,
                                              float* __restrict__ out) {
    extern __shared__ float smem[];
    float* Cts = smem;                 // [128][128], Cts[c][o]
    float* xs  = smem + CH * CH;       // [128][64]
    float* d_s = xs + CH * 64;         // [128]

    int b = blockIdx.y;
    int s0 = blockIdx.x * 64;
    int t = threadIdx.x;

    const float4* Ct4 = (const float4*)&g_Ct[b][0][0];
    float4* Cts4 = (float4*)Cts;
    for (int idx = t; idx < CH * CH / 4; idx += 256) Cts4[idx] = Ct4[idx];

    const float* xb = x + (size_t)b * BSTRIDE + s0;
    float4* xs4 = (float4*)xs;
    for (int idx = t; idx < CH * 16; idx += 256) {
        int row = idx >> 4, c4 = idx & 15;
        xs4[row * 16 + c4] = *(const float4*)(xb + row * SP + c4 * 4);
    }
    if (t < CH) d_s[t] = g_d[b][t];
    __syncthreads();

    int sx = t & 15, oy = t >> 4;       // 4 spatial cols, 8 output rows
    u64 acc2[8][2];
    #pragma unroll
    for (int i = 0; i < 8; ++i) { acc2[i][0] = 0ull; acc2[i][1] = 0ull; }

    for (int c = 0; c < CH; ++c) {
        u64 x0 = *(const u64*)&xs[c * 64 + sx * 4];       // 16B aligned
        u64 x1 = *(const u64*)&xs[c * 64 + sx * 4 + 2];   // 8B aligned
        float4 a0 = Cts4[c * 32 + oy * 2];
        float4 a1 = Cts4[c * 32 + oy * 2 + 1];
        float av[8] = {a0.x, a0.y, a0.z, a0.w, a1.x, a1.y, a1.z, a1.w};
        #pragma unroll
        for (int rr = 0; rr < 8; ++rr) {
            u64 ab = pack2(av[rr], av[rr]);
            fma2(acc2[rr][0], ab, x0);
            fma2(acc2[rr][1], ab, x1);
        }
    }

    float* ob = out + (size_t)b * BSTRIDE + s0;
    #pragma unroll
    for (int rr = 0; rr < 8; ++rr) {
        int ro = oy * 8 + rr;
        float dd = d_s[ro];
        float4 xv = xs4[ro * 16 + sx];
        float2 v0 = unpack2(acc2[rr][0]);
        float2 v1 = unpack2(acc2[rr][1]);
        float4 o;
        o.x = xv.x + v0.x + dd;
        o.y = xv.y + v0.y + dd;
        o.z = xv.z + v1.x + dd;
        o.w = xv.w + v1.y + dd;
        *(float4*)(ob + ro * SP + sx * 4) = o;
    }
}

extern "C" void kernel_launch(void* const* d_in, const int* in_sizes, int n_in,
                              void* d_out, int out_size) {
    const float* x    = (const float*)d_in[0];
    const float* gn_w = (const float*)d_in[1];
    const float* gn_b = (const float*)d_in[2];
    const float* w_in = (const float*)d_in[3];
    const float* b_in = (const float*)d_in[4];
    const float* w_out= (const float*)d_in[5];
    const float* b_out= (const float*)d_in[6];
    float* out = (float*)d_out;
    (void)in_sizes; (void)n_in; (void)out_size;

    cudaFuncSetAttribute(k_main,  cudaFuncAttributeMaxDynamicSharedMemorySize, SMEM_MAIN);
    cudaFuncSetAttribute(k_prep2, cudaFuncAttributeMaxDynamicSharedMemorySize, SMEM_P2);

    k_zero<<<512, 256>>>();
    dim3 gs(3, 16, NB);
    k_syrk<<<gs, 256>>>(x);
    k_prep1<<<NB, 128>>>(gn_w, gn_b, w_in, b_in);
    k_prep2<<<64, 256, SMEM_P2>>>(w_in, w_out);
    k_prep3<<<dim3(8, NB), 128>>>(w_in, b_out);
    k_main<<<dim3(SP / 64, NB), 256, SMEM_MAIN>>>(x, out);
}

// round 4
// speedup vs baseline: 1.2300x; 1.1045x over previous
#include <cuda_runtime.h>

#define CH 128
#define NB 8
#define SP 16384              // spatial = 128*128
#define BSTRIDE (CH*SP)
#define GROUPS 8
#define GSIZE 16
#define HEADS 8
#define HD 16
#define EPS 1e-5f

typedef unsigned long long u64;

// packed fp32x2 helpers (Blackwell f32x2 pipe: 2 MACs per fma slot)
__device__ __forceinline__ u64 pack2(float lo, float hi) {
    u64 r; asm("mov.b64 %0, {%1,%2};" : "=l"(r) : "f"(lo), "f"(hi)); return r;
}
__device__ __forceinline__ void fma2(u64& d, u64 a, u64 b) {
    asm("fma.rn.f32x2 %0, %1, %2, %0;" : "+l"(d) : "l"(a), "l"(b));
}
__device__ __forceinline__ float2 unpack2(u64 v) {
    float2 f; asm("mov.b64 {%0,%1}, %2;" : "=f"(f.x), "=f"(f.y) : "l"(v)); return f;
}

// -------- device scratch (no allocs allowed) --------
__device__ float g_S[NB][CH][CH];     // per-batch X X^T
__device__ float g_r[NB][CH];         // per-batch row sums of X
__device__ float g_alpha[NB][CH];
__device__ float g_Bp[NB][CH];        // B' (effective bias after GN+conv_in)
__device__ float g_u[NB][CH];         // W' r
__device__ float g_M[NB][CH][CH];     // conv_out composed with softmax weights
__device__ float g_Ct[NB][CH][CH];    // (C + I) transposed: g_Ct[b][c][o]
__device__ float g_d[NB][CH];

// -------- zero scratch (graph replays reuse globals) --------
__global__ void k_zero() {
    int idx = blockIdx.x * blockDim.x + threadIdx.x;
    if (idx < NB*CH*CH) ((float*)g_S)[idx] = 0.f;
    if (idx < NB*CH)    ((float*)g_r)[idx] = 0.f;
}

// -------- kernel 1: per-batch syrk S = X X^T (upper tiles) + row sums --------
// grid (3 tiles, 16 s-splits, 8 batches), 128 threads, 64x64 tile, 8x4/thread
__global__ __launch_bounds__(128) void k_syrk(const float* __restrict__ x) {
    int b = blockIdx.z;
    int tile = blockIdx.x;            // 0:(0,0) 1:(0,1) 2:(1,1) in 64x64 tiles
    int ti = (tile == 2) ? 1 : 0;
    int tj = (tile == 0) ? 0 : 1;
    int arow0 = ti * 64, brow0 = tj * 64;
    int s0 = blockIdx.y * 1024;
    bool diag = (ti == tj);

    __shared__ __align__(16) float As[16][68];
    __shared__ __align__(16) float Bs[16][68];

    int t = threadIdx.x;
    int r = t >> 1, q = t & 1;        // loader: row r (0..63), col-half q (8 floats)
    int tx = t & 15, ty = t >> 4;     // compute: tx->4 cols, ty->8 rows

    u64 acc2[4][4];                   // [i-pair][j]
    #pragma unroll
    for (int p = 0; p < 4; ++p)
        #pragma unroll
        for (int j = 0; j < 4; ++j) acc2[p][j] = 0ull;
    float rsum = 0.f;

    const float* xb = x + (size_t)b * BSTRIDE;
    const float* pa = xb + (arow0 + r) * SP + s0 + 8 * q;
    const float* pb = xb + (brow0 + r) * SP + s0 + 8 * q;

    // prefetch first chunk
    float4 av0 = *(const float4*)(pa + 0);
    float4 av1 = *(const float4*)(pa + 4);
    float4 bv0 = *(const float4*)(pb + 0);
    float4 bv1 = *(const float4*)(pb + 4);

    for (int ch = 0; ch < 64; ++ch) {
        __syncthreads();              // previous compute done reading smem
        int c0 = 8 * q;
        As[c0+0][r] = av0.x; As[c0+1][r] = av0.y; As[c0+2][r] = av0.z; As[c0+3][r] = av0.w;
        As[c0+4][r] = av1.x; As[c0+5][r] = av1.y; As[c0+6][r] = av1.z; As[c0+7][r] = av1.w;
        Bs[c0+0][r] = bv0.x; Bs[c0+1][r] = bv0.y; Bs[c0+2][r] = bv0.z; Bs[c0+3][r] = bv0.w;
        Bs[c0+4][r] = bv1.x; Bs[c0+5][r] = bv1.y; Bs[c0+6][r] = bv1.z; Bs[c0+7][r] = bv1.w;
        if (diag) rsum += av0.x + av0.y + av0.z + av0.w + av1.x + av1.y + av1.z + av1.w;
        __syncthreads();
        if (ch < 63) {                // issue next loads early: latency hidden by compute
            const float* na = pa + (ch + 1) * 16;
            const float* nb = pb + (ch + 1) * 16;
            av0 = *(const float4*)(na + 0);
            av1 = *(const float4*)(na + 4);
            bv0 = *(const float4*)(nb + 0);
            bv1 = *(const float4*)(nb + 4);
        }
        #pragma unroll
        for (int k = 0; k < 16; ++k) {
            // a: 8 rows as 4 native u64 pairs (rows contiguous in As[k][.])
            u64 a0 = *(const u64*)&As[k][8*ty + 0];
            u64 a1 = *(const u64*)&As[k][8*ty + 2];
            u64 a2 = *(const u64*)&As[k][8*ty + 4];
            u64 a3 = *(const u64*)&As[k][8*ty + 6];
            float4 bv = *(const float4*)&Bs[k][4*tx];
            u64 bb0 = pack2(bv.x, bv.x);
            u64 bb1 = pack2(bv.y, bv.y);
            u64 bb2 = pack2(bv.z, bv.z);
            u64 bb3 = pack2(bv.w, bv.w);
            fma2(acc2[0][0], a0, bb0); fma2(acc2[0][1], a0, bb1);
            fma2(acc2[0][2], a0, bb2); fma2(acc2[0][3], a0, bb3);
            fma2(acc2[1][0], a1, bb0); fma2(acc2[1][1], a1, bb1);
            fma2(acc2[1][2], a1, bb2); fma2(acc2[1][3], a1, bb3);
            fma2(acc2[2][0], a2, bb0); fma2(acc2[2][1], a2, bb1);
            fma2(acc2[2][2], a2, bb2); fma2(acc2[2][3], a2, bb3);
            fma2(acc2[3][0], a3, bb0); fma2(acc2[3][1], a3, bb1);
            fma2(acc2[3][2], a3, bb2); fma2(acc2[3][3], a3, bb3);
        }
    }
    #pragma unroll
    for (int p = 0; p < 4; ++p)
        #pragma unroll
        for (int j = 0; j < 4; ++j) {
            float2 v = unpack2(acc2[p][j]);
            atomicAdd(&g_S[b][arow0 + 8*ty + 2*p + 0][brow0 + 4*tx + j], v.x);
            atomicAdd(&g_S[b][arow0 + 8*ty + 2*p + 1][brow0 + 4*tx + j], v.y);
        }
    if (diag) atomicAdd(&g_r[b][arow0 + r], rsum);
}

// -------- prep1: GN stats from S diag + r, alpha/beta, B', u, mirror S --------
__global__ __launch_bounds__(128) void k_prep1(const float* __restrict__ gn_w,
                                               const float* __restrict__ gn_b,
                                               const float* __restrict__ w_in,
                                               const float* __restrict__ b_in) {
    int b = blockIdx.x;
    int t = threadIdx.x;   // channel
    __shared__ float r_s[CH], sq_s[CH], alpha_s[CH], beta_s[CH];
    r_s[t]  = g_r[b][t];
    sq_s[t] = g_S[b][t][t];
    __syncthreads();
    int g0 = (t >> 4) << 4;
    float sum = 0.f, sumsq = 0.f;
    #pragma unroll
    for (int i = 0; i < GSIZE; ++i) { sum += r_s[g0 + i]; sumsq += sq_s[g0 + i]; }
    const float inv_cnt = 1.f / (float)(GSIZE * SP);
    float mu  = sum * inv_cnt;
    float var = sumsq * inv_cnt - mu * mu;
    float al = gn_w[t] * rsqrtf(var + EPS);
    float be = gn_b[t] - mu * al;
    alpha_s[t] = al; beta_s[t] = be;
    g_alpha[b][t] = al;
    __syncthreads();
    float bp = b_in[t], uu = 0.f;
    const float* wrow = w_in + t * CH;
    for (int c = 0; c < CH; ++c) {
        float w = wrow[c];
        bp += w * beta_s[c];
        uu += w * alpha_s[c] * r_s[c];
    }
    g_Bp[b][t] = bp;
    g_u[b][t]  = uu;
    // mirror S lower-left from upper-right
    for (int idx = t; idx < 64 * 64; idx += 128) {
        int i = idx >> 6, j = idx & 63;
        g_S[b][64 + i][j] = g_S[b][j][64 + i];
    }
}

// -------- prep2: per (b,h) Gram block -> softmax -> M column block --------
// grid 64 (b*8+h), 256 threads; S staged with padded stride; symmetric row reads
#define SSTR 132
#define SMEM_P2 ((CH*SSTR + 2*16*SSTR + 2*16*17) * 4)
__global__ __launch_bounds__(256) void k_prep2(const float* __restrict__ w_in,
                                               const float* __restrict__ w_out) {
    extern __shared__ float sm2[];
    float* Ss  = sm2;                       // [128][SSTR]
    float* Whs = Ss + CH * SSTR;            // [16][SSTR]
    float* Ts  = Whs + 16 * SSTR;           // [16][SSTR]
    float* sc  = Ts + 16 * SSTR;            // [16][17]
    float* Wt  = sc + 16 * 17;              // [16][17]

    int b = blockIdx.x >> 3, h = blockIdx.x & 7;
    int t = threadIdx.x;

    // stage S (coalesced float4, padded rows)
    {
        const float4* src = (const float4*)&g_S[b][0][0];
        for (int idx = t; idx < CH * CH / 4; idx += 256) {
            int row = idx >> 5, c4 = idx & 31;
            *(float4*)&Ss[row * SSTR + 4 * c4] = src[idx];
        }
    }
    for (int idx = t; idx < 16 * CH; idx += 256) {
        int i = idx >> 7, k = idx & 127;
        Whs[i * SSTR + k] = w_in[(h * 16 + i) * CH + k] * g_alpha[b][k];
    }
    __syncthreads();

    // T = Wh * S ; use S symmetry: S[l][k] read from row l (contiguous float4)
    {
        int l = t & 127, ih = (t >> 7) * 8;
        float ta[8];
        #pragma unroll
        for (int i = 0; i < 8; ++i) ta[i] = 0.f;
        for (int k4 = 0; k4 < 32; ++k4) {
            float4 sv = *(const float4*)&Ss[l * SSTR + 4 * k4];
            #pragma unroll
            for (int i = 0; i < 8; ++i) {
                float4 wv = *(const float4*)&Whs[(ih + i) * SSTR + 4 * k4];
                ta[i] += wv.x * sv.x + wv.y * sv.y + wv.z * sv.z + wv.w * sv.w;
            }
        }
        #pragma unroll
        for (int i = 0; i < 8; ++i) Ts[(ih + i) * SSTR + l] = ta[i];
    }
    __syncthreads();

    // Gram + rank-1 terms: thread = (i = t>>4, j = t&15)
    {
        int i = t >> 4, j = t & 15;
        float g = 0.f;
        for (int l4 = 0; l4 < 32; ++l4) {
            float4 tv = *(const float4*)&Ts[i * SSTR + 4 * l4];
            float4 wv = *(const float4*)&Whs[j * SSTR + 4 * l4];
            g += tv.x * wv.x + tv.y * wv.y + tv.z * wv.z + tv.w * wv.w;
        }
        float ui = g_u[b][h*16 + i], bi = g_Bp[b][h*16 + i];
        float uj = g_u[b][h*16 + j], bj = g_Bp[b][h*16 + j];
        sc[i * 17 + j] = 0.25f * (g + ui*bj + bi*uj + (float)SP * bi * bj);
    }
    __syncthreads();

    if (t < 16) {
        float m = sc[t * 17 + 0];
        #pragma unroll
        for (int j = 1; j < 16; ++j) m = fmaxf(m, sc[t * 17 + j]);
        float e[16], s = 0.f;
        #pragma unroll
        for (int j = 0; j < 16; ++j) { e[j] = expf(sc[t * 17 + j] - m); s += e[j]; }
        float inv = 1.f / s;
        #pragma unroll
        for (int j = 0; j < 16; ++j) Wt[t * 17 + j] = e[j] * inv;
    }
    __syncthreads();

    // M[o][h*16+j] = sum_i w_out[o][h*16+i] * Wt[i][j]
    {
        int o = t & 127, jh = (t >> 7) * 8;
        float wo[16];
        #pragma unroll
        for (int i = 0; i < 16; ++i) wo[i] = w_out[o * CH + h * 16 + i];
        #pragma unroll
        for (int j = 0; j < 8; ++j) {
            float m = 0.f;
            #pragma unroll
            for (int i = 0; i < 16; ++i) m += wo[i] * Wt[i * 17 + jh + j];
            g_M[b][o][h * 16 + jh + j] = m;
        }
    }
}

// -------- prep3: Ct = (M W')^T + I stored [c][o], and d = M B' + b_out --------
__global__ __launch_bounds__(128) void k_prep3(const float* __restrict__ w_in,
                                               const float* __restrict__ b_out) {
    int b = blockIdx.y, o0 = blockIdx.x * 16;
    int t = threadIdx.x;  // = c
    __shared__ float Ms[16][CH];
    __shared__ float Bp_s[CH];
    for (int idx = t; idx < 16 * CH; idx += 128) {
        int i = idx >> 7, k = idx & 127;
        Ms[i][k] = g_M[b][o0 + i][k];
    }
    Bp_s[t] = g_Bp[b][t];
    __syncthreads();
    float a[16];
    #pragma unroll
    for (int i = 0; i < 16; ++i) a[i] = 0.f;
    for (int k = 0; k < CH; ++k) {
        float wv = w_in[k * CH + t];
        #pragma unroll
        for (int i = 0; i < 16; ++i) a[i] += Ms[i][k] * wv;
    }
    float al = g_alpha[b][t];
    #pragma unroll
    for (int i = 0; i < 16; ++i) {
        float v = al * a[i];
        if (o0 + i == t) v += 1.0f;     // fold residual identity
        g_Ct[b][t][o0 + i] = v;
    }
    if (t < 16) {
        float dv = b_out[o0 + t];
        for (int k = 0; k < CH; ++k) dv += Ms[t][k] * Bp_s[k];
        g_d[b][o0 + t] = dv;
    }
}

// -------- main: out = (I+C) x + d ; 4 s-tiles per block, Ct loaded once --------
#define TILES_PER_BLK 4
#define SMEM_MAIN ((CH*CH + CH*64 + CH) * 4)
__global__ __launch_bounds__(256) void k_main(const float* __restrict__ x,
                                              float* __restrict__ out) {
    extern __shared__ float smem[];
    float* Cts = smem;                 // [128][128], Cts[c][o]
    float* xs  = smem + CH * CH;       // [128][64]
    float* d_s = xs + CH * 64;         // [128]

    int b = blockIdx.y;
    int base = blockIdx.x * (64 * TILES_PER_BLK);
    int t = threadIdx.x;

    // load Ct (once per block)
    {
        const float4* Ct4 = (const float4*)&g_Ct[b][0][0];
        float4* Cts4 = (float4*)Cts;
        for (int idx = t; idx < CH * CH / 4; idx += 256) Cts4[idx] = Ct4[idx];
        if (t < CH) d_s[t] = g_d[b][t];
    }

    int sx = t & 15, oy = t >> 4;      // 4 spatial cols, 16 oy -> 8 o-rows each

    const float* xb = x + (size_t)b * BSTRIDE + base;
    float* ob = out + (size_t)b * BSTRIDE + base;

    // prefetch first x tile into registers (8 float4/thread)
    float4 pre[8];
    #pragma unroll
    for (int w = 0; w < 8; ++w) {
        int idx = t + 256 * w;
        int row = idx >> 4, c4 = idx & 15;
        pre[w] = *(const float4*)(xb + row * SP + c4 * 4);
    }

    for (int it = 0; it < TILES_PER_BLK; ++it) {
        __syncthreads();               // prev compute done reading xs (also orders Ct)
        #pragma unroll
        for (int w = 0; w < 8; ++w) {
            int idx = t + 256 * w;
            int row = idx >> 4, c4 = idx & 15;
            *(float4*)&xs[row * 64 + c4 * 4] = pre[w];
        }
        __syncthreads();
        if (it + 1 < TILES_PER_BLK) {  // prefetch next tile during compute
            #pragma unroll
            for (int w = 0; w < 8; ++w) {
                int idx = t + 256 * w;
                int row = idx >> 4, c4 = idx & 15;
                pre[w] = *(const float4*)(xb + (it + 1) * 64 + row * SP + c4 * 4);
            }
        }

        u64 acc2[4][4];                // [o-pair][s]
        #pragma unroll
        for (int p = 0; p < 4; ++p)
            #pragma unroll
            for (int j = 0; j < 4; ++j) acc2[p][j] = 0ull;

        for (int c = 0; c < CH; ++c) {
            u64 c0 = *(const u64*)&Cts[c * CH + 8*oy + 0];   // native o-pairs
            u64 c1 = *(const u64*)&Cts[c * CH + 8*oy + 2];
            u64 c2 = *(const u64*)&Cts[c * CH + 8*oy + 4];
            u64 c3 = *(const u64*)&Cts[c * CH + 8*oy + 6];
            float4 xv = *(const float4*)&xs[c * 64 + 4*sx];
            u64 xx0 = pack2(xv.x, xv.x);
            u64 xx1 = pack2(xv.y, xv.y);
            u64 xx2 = pack2(xv.z, xv.z);
            u64 xx3 = pack2(xv.w, xv.w);
            fma2(acc2[0][0], c0, xx0); fma2(acc2[0][1], c0, xx1);
            fma2(acc2[0][2], c0, xx2); fma2(acc2[0][3], c0, xx3);
            fma2(acc2[1][0], c1, xx0); fma2(acc2[1][1], c1, xx1);
            fma2(acc2[1][2], c1, xx2); fma2(acc2[1][3], c1, xx3);
            fma2(acc2[2][0], c2, xx0); fma2(acc2[2][1], c2, xx1);
            fma2(acc2[2][2], c2, xx2); fma2(acc2[2][3], c2, xx3);
            fma2(acc2[3][0], c3, xx0); fma2(acc2[3][1], c3, xx1);
            fma2(acc2[3][2], c3, xx2); fma2(acc2[3][3], c3, xx3);
        }

        float* obt = ob + it * 64;
        #pragma unroll
        for (int p = 0; p < 4; ++p) {
            int o0 = 8*oy + 2*p;
            float2 v0 = unpack2(acc2[p][0]);
            float2 v1 = unpack2(acc2[p][1]);
            float2 v2 = unpack2(acc2[p][2]);
            float2 v3 = unpack2(acc2[p][3]);
            float d0 = d_s[o0], d1 = d_s[o0 + 1];
            float4 r0 = { v0.x + d0, v1.x + d0, v2.x + d0, v3.x + d0 };
            float4 r1 = { v0.y + d1, v1.y + d1, v2.y + d1, v3.y + d1 };
            *(float4*)(obt + o0 * SP + 4*sx) = r0;
            *(float4*)(obt + (o0 + 1) * SP + 4*sx) = r1;
        }
    }
}

extern "C" void kernel_launch(void* const* d_in, const int* in_sizes, int n_in,
                              void* d_out, int out_size) {
    const float* x    = (const float*)d_in[0];
    const float* gn_w = (const float*)d_in[1];
    const float* gn_b = (const float*)d_in[2];
    const float* w_in = (const float*)d_in[3];
    const float* b_in = (const float*)d_in[4];
    const float* w_out= (const float*)d_in[5];
    const float* b_out= (const float*)d_in[6];
    float* out = (float*)d_out;
    (void)in_sizes; (void)n_in; (void)out_size;

    cudaFuncSetAttribute(k_main,  cudaFuncAttributeMaxDynamicSharedMemorySize, SMEM_MAIN);
    cudaFuncSetAttribute(k_prep2, cudaFuncAttributeMaxDynamicSharedMemorySize, SMEM_P2);

    k_zero<<<512, 256>>>();
    dim3 gs(3, 16, NB);
    k_syrk<<<gs, 128>>>(x);
    k_prep1<<<NB, 128>>>(gn_w, gn_b, w_in, b_in);
    k_prep2<<<64, 256, SMEM_P2>>>(w_in, w_out);
    k_prep3<<<dim3(8, NB), 128>>>(w_in, b_out);
    k_main<<<dim3(SP / (64 * TILES_PER_BLK), NB), 256, SMEM_MAIN>>>(x, out);
}

// round 5
// speedup vs baseline: 1.2415x; 1.0093x over previous
#include <cuda_runtime.h>

#define CH 128
#define NB 8
#define SP 16384              // spatial = 128*128
#define BSTRIDE (CH*SP)
#define GROUPS 8
#define GSIZE 16
#define HEADS 8
#define HD 16
#define EPS 1e-5f

typedef unsigned long long u64;

// packed fp32x2 helpers (Blackwell f32x2 pipe: 2 MACs per fma slot)
__device__ __forceinline__ u64 pack2(float lo, float hi) {
    u64 r; asm("mov.b64 %0, {%1,%2};" : "=l"(r) : "f"(lo), "f"(hi)); return r;
}
__device__ __forceinline__ void fma2(u64& d, u64 a, u64 b) {
    asm("fma.rn.f32x2 %0, %1, %2, %0;" : "+l"(d) : "l"(a), "l"(b));
}
__device__ __forceinline__ float2 unpack2(u64 v) {
    float2 f; asm("mov.b64 {%0,%1}, %2;" : "=f"(f.x), "=f"(f.y) : "l"(v)); return f;
}

// -------- device scratch (no allocs allowed) --------
__device__ float g_S[NB][CH][CH];     // per-batch X X^T
__device__ float g_r[NB][CH];         // per-batch row sums of X
__device__ float g_alpha[NB][CH];
__device__ float g_Bp[NB][CH];        // B' (effective bias after GN+conv_in)
__device__ float g_u[NB][CH];         // W' r
__device__ float g_M[NB][CH][CH];     // conv_out composed with softmax weights
__device__ float g_Ct[NB][CH][CH];    // (C + I) transposed: g_Ct[b][c][o]
__device__ float g_d[NB][CH];

// -------- zero scratch (graph replays reuse globals) --------
__global__ void k_zero() {
    int idx = blockIdx.x * blockDim.x + threadIdx.x;
    if (idx < NB*CH*CH) ((float*)g_S)[idx] = 0.f;
    if (idx < NB*CH)    ((float*)g_r)[idx] = 0.f;
}

// -------- kernel 1: per-batch syrk S = X X^T (upper tiles) + row sums --------
// grid (3 tiles, 16 s-splits, 8 batches), 128 threads, 64x64 tile, 8x4/thread
__global__ __launch_bounds__(128) void k_syrk(const float* __restrict__ x) {
    int b = blockIdx.z;
    int tile = blockIdx.x;            // 0:(0,0) 1:(0,1) 2:(1,1) in 64x64 tiles
    int ti = (tile == 2) ? 1 : 0;
    int tj = (tile == 0) ? 0 : 1;
    int arow0 = ti * 64, brow0 = tj * 64;
    int s0 = blockIdx.y * 1024;
    bool diag = (ti == tj);

    __shared__ __align__(16) float As[16][68];
    __shared__ __align__(16) float Bs[16][68];

    int t = threadIdx.x;
    int r = t >> 1, q = t & 1;        // loader: row r (0..63), col-half q (8 floats)
    int tx = t & 15, ty = t >> 4;     // compute: tx->4 cols, ty->8 rows

    u64 acc2[4][4];                   // [i-pair][j]
    #pragma unroll
    for (int p = 0; p < 4; ++p)
        #pragma unroll
        for (int j = 0; j < 4; ++j) acc2[p][j] = 0ull;
    float rsum = 0.f;

    const float* xb = x + (size_t)b * BSTRIDE;
    const float* pa = xb + (arow0 + r) * SP + s0 + 8 * q;
    const float* pb = xb + (brow0 + r) * SP + s0 + 8 * q;

    // prefetch first chunk
    float4 av0 = *(const float4*)(pa + 0);
    float4 av1 = *(const float4*)(pa + 4);
    float4 bv0 = *(const float4*)(pb + 0);
    float4 bv1 = *(const float4*)(pb + 4);

    for (int ch = 0; ch < 64; ++ch) {
        __syncthreads();              // previous compute done reading smem
        int c0 = 8 * q;
        As[c0+0][r] = av0.x; As[c0+1][r] = av0.y; As[c0+2][r] = av0.z; As[c0+3][r] = av0.w;
        As[c0+4][r] = av1.x; As[c0+5][r] = av1.y; As[c0+6][r] = av1.z; As[c0+7][r] = av1.w;
        Bs[c0+0][r] = bv0.x; Bs[c0+1][r] = bv0.y; Bs[c0+2][r] = bv0.z; Bs[c0+3][r] = bv0.w;
        Bs[c0+4][r] = bv1.x; Bs[c0+5][r] = bv1.y; Bs[c0+6][r] = bv1.z; Bs[c0+7][r] = bv1.w;
        if (diag) rsum += av0.x + av0.y + av0.z + av0.w + av1.x + av1.y + av1.z + av1.w;
        __syncthreads();
        if (ch < 63) {                // issue next loads early: latency hidden by compute
            const float* na = pa + (ch + 1) * 16;
            const float* nb = pb + (ch + 1) * 16;
            av0 = *(const float4*)(na + 0);
            av1 = *(const float4*)(na + 4);
            bv0 = *(const float4*)(nb + 0);
            bv1 = *(const float4*)(nb + 4);
        }
        #pragma unroll
        for (int k = 0; k < 16; ++k) {
            u64 a0 = *(const u64*)&As[k][8*ty + 0];
            u64 a1 = *(const u64*)&As[k][8*ty + 2];
            u64 a2 = *(const u64*)&As[k][8*ty + 4];
            u64 a3 = *(const u64*)&As[k][8*ty + 6];
            float4 bv = *(const float4*)&Bs[k][4*tx];
            u64 bb0 = pack2(bv.x, bv.x);
            u64 bb1 = pack2(bv.y, bv.y);
            u64 bb2 = pack2(bv.z, bv.z);
            u64 bb3 = pack2(bv.w, bv.w);
            fma2(acc2[0][0], a0, bb0); fma2(acc2[0][1], a0, bb1);
            fma2(acc2[0][2], a0, bb2); fma2(acc2[0][3], a0, bb3);
            fma2(acc2[1][0], a1, bb0); fma2(acc2[1][1], a1, bb1);
            fma2(acc2[1][2], a1, bb2); fma2(acc2[1][3], a1, bb3);
            fma2(acc2[2][0], a2, bb0); fma2(acc2[2][1], a2, bb1);
            fma2(acc2[2][2], a2, bb2); fma2(acc2[2][3], a2, bb3);
            fma2(acc2[3][0], a3, bb0); fma2(acc2[3][1], a3, bb1);
            fma2(acc2[3][2], a3, bb2); fma2(acc2[3][3], a3, bb3);
        }
    }
    #pragma unroll
    for (int p = 0; p < 4; ++p)
        #pragma unroll
        for (int j = 0; j < 4; ++j) {
            float2 v = unpack2(acc2[p][j]);
            atomicAdd(&g_S[b][arow0 + 8*ty + 2*p + 0][brow0 + 4*tx + j], v.x);
            atomicAdd(&g_S[b][arow0 + 8*ty + 2*p + 1][brow0 + 4*tx + j], v.y);
        }
    if (diag) atomicAdd(&g_r[b][arow0 + r], rsum);
}

// -------- prep1: GN stats from S diag + r, alpha/beta, B', u, mirror S --------
__global__ __launch_bounds__(128) void k_prep1(const float* __restrict__ gn_w,
                                               const float* __restrict__ gn_b,
                                               const float* __restrict__ w_in,
                                               const float* __restrict__ b_in) {
    int b = blockIdx.x;
    int t = threadIdx.x;   // channel
    __shared__ float r_s[CH], sq_s[CH], alpha_s[CH], beta_s[CH];
    r_s[t]  = g_r[b][t];
    sq_s[t] = g_S[b][t][t];
    __syncthreads();
    int g0 = (t >> 4) << 4;
    float sum = 0.f, sumsq = 0.f;
    #pragma unroll
    for (int i = 0; i < GSIZE; ++i) { sum += r_s[g0 + i]; sumsq += sq_s[g0 + i]; }
    const float inv_cnt = 1.f / (float)(GSIZE * SP);
    float mu  = sum * inv_cnt;
    float var = sumsq * inv_cnt - mu * mu;
    float al = gn_w[t] * rsqrtf(var + EPS);
    float be = gn_b[t] - mu * al;
    alpha_s[t] = al; beta_s[t] = be;
    g_alpha[b][t] = al;
    __syncthreads();
    float bp = b_in[t], uu = 0.f;
    const float* wrow = w_in + t * CH;
    for (int c = 0; c < CH; ++c) {
        float w = wrow[c];
        bp += w * beta_s[c];
        uu += w * alpha_s[c] * r_s[c];
    }
    g_Bp[b][t] = bp;
    g_u[b][t]  = uu;
    // mirror S lower-left from upper-right
    for (int idx = t; idx < 64 * 64; idx += 128) {
        int i = idx >> 6, j = idx & 63;
        g_S[b][64 + i][j] = g_S[b][j][64 + i];
    }
}

// -------- prep2: per (b,h) Gram block -> softmax -> M column block --------
// grid 64 (b*8+h), 512 threads; conflict-free lane mapping (l = t>>2)
#define SSTR 132
#define SMEM_P2 ((CH*SSTR + 2*16*SSTR + 2*16*17) * 4)
__global__ __launch_bounds__(512) void k_prep2(const float* __restrict__ w_in,
                                               const float* __restrict__ w_out) {
    extern __shared__ float sm2[];
    float* Ss  = sm2;                       // [128][SSTR]
    float* Whs = Ss + CH * SSTR;            // [16][SSTR]
    float* Ts  = Whs + 16 * SSTR;           // [16][SSTR]
    float* sc  = Ts + 16 * SSTR;            // [16][17]
    float* Wt  = sc + 16 * 17;              // [16][17]

    int b = blockIdx.x >> 3, h = blockIdx.x & 7;
    int t = threadIdx.x;

    // stage S (coalesced float4, padded rows)
    {
        const float4* src = (const float4*)&g_S[b][0][0];
        for (int idx = t; idx < CH * CH / 4; idx += 512) {
            int row = idx >> 5, c4 = idx & 31;
            *(float4*)&Ss[row * SSTR + 4 * c4] = src[idx];
        }
    }
    for (int idx = t; idx < 16 * CH; idx += 512) {
        int i = idx >> 7, k = idx & 127;
        Whs[i * SSTR + k] = w_in[(h * 16 + i) * CH + k] * g_alpha[b][k];
    }
    __syncthreads();

    // T = Wh * S ; warp-friendly map: l = t>>2 (8 distinct rows/warp, bank-free),
    // ihb = (t&3)*4 (4 T-rows per thread)
    {
        int l = t >> 2, ihb = (t & 3) * 4;
        float ta[4];
        #pragma unroll
        for (int i = 0; i < 4; ++i) ta[i] = 0.f;
        for (int k4 = 0; k4 < 32; ++k4) {
            float4 sv = *(const float4*)&Ss[l * SSTR + 4 * k4];   // S row l (symmetry)
            #pragma unroll
            for (int i = 0; i < 4; ++i) {
                float4 wv = *(const float4*)&Whs[(ihb + i) * SSTR + 4 * k4];
                ta[i] += wv.x * sv.x + wv.y * sv.y + wv.z * sv.z + wv.w * sv.w;
            }
        }
        #pragma unroll
        for (int i = 0; i < 4; ++i) Ts[(ihb + i) * SSTR + l] = ta[i];
    }
    __syncthreads();

    // Gram + rank-1 terms: threads 0..255 -> (i = t>>4, j = t&15)
    if (t < 256) {
        int i = t >> 4, j = t & 15;
        float g = 0.f;
        for (int l4 = 0; l4 < 32; ++l4) {
            float4 tv = *(const float4*)&Ts[i * SSTR + 4 * l4];
            float4 wv = *(const float4*)&Whs[j * SSTR + 4 * l4];
            g += tv.x * wv.x + tv.y * wv.y + tv.z * wv.z + tv.w * wv.w;
        }
        float ui = g_u[b][h*16 + i], bi = g_Bp[b][h*16 + i];
        float uj = g_u[b][h*16 + j], bj = g_Bp[b][h*16 + j];
        sc[i * 17 + j] = 0.25f * (g + ui*bj + bi*uj + (float)SP * bi * bj);
    }
    __syncthreads();

    if (t < 16) {
        float m = sc[t * 17 + 0];
        #pragma unroll
        for (int j = 1; j < 16; ++j) m = fmaxf(m, sc[t * 17 + j]);
        float e[16], s = 0.f;
        #pragma unroll
        for (int j = 0; j < 16; ++j) { e[j] = expf(sc[t * 17 + j] - m); s += e[j]; }
        float inv = 1.f / s;
        #pragma unroll
        for (int j = 0; j < 16; ++j) Wt[t * 17 + j] = e[j] * inv;
    }
    __syncthreads();

    // M[o][h*16+j] = sum_i w_out[o][h*16+i] * Wt[i][j]; o = t>>2, jhb = (t&3)*4
    {
        int o = t >> 2, jhb = (t & 3) * 4;
        float wo[16];
        #pragma unroll
        for (int i = 0; i < 16; ++i) wo[i] = w_out[o * CH + h * 16 + i];
        #pragma unroll
        for (int j = 0; j < 4; ++j) {
            float m = 0.f;
            #pragma unroll
            for (int i = 0; i < 16; ++i) m += wo[i] * Wt[i * 17 + jhb + j];
            g_M[b][o][h * 16 + jhb + j] = m;
        }
    }
}

// -------- prep3: Ct = (M W')^T + I stored [c][o], and d = M B' + b_out --------
__global__ __launch_bounds__(128) void k_prep3(const float* __restrict__ w_in,
                                               const float* __restrict__ b_out) {
    int b = blockIdx.y, o0 = blockIdx.x * 16;
    int t = threadIdx.x;  // = c
    __shared__ float Ms[16][CH];
    __shared__ float Bp_s[CH];
    for (int idx = t; idx < 16 * CH; idx += 128) {
        int i = idx >> 7, k = idx & 127;
        Ms[i][k] = g_M[b][o0 + i][k];
    }
    Bp_s[t] = g_Bp[b][t];
    __syncthreads();
    float a[16];
    #pragma unroll
    for (int i = 0; i < 16; ++i) a[i] = 0.f;
    for (int k = 0; k < CH; ++k) {
        float wv = w_in[k * CH + t];
        #pragma unroll
        for (int i = 0; i < 16; ++i) a[i] += Ms[i][k] * wv;
    }
    float al = g_alpha[b][t];
    #pragma unroll
    for (int i = 0; i < 16; ++i) {
        float v = al * a[i];
        if (o0 + i == t) v += 1.0f;     // fold residual identity
        g_Ct[b][t][o0 + i] = v;
    }
    if (t < 16) {
        float dv = b_out[o0 + t];
        for (int k = 0; k < CH; ++k) dv += Ms[t][k] * Bp_s[k];
        g_d[b][o0 + t] = dv;
    }
}

// -------- main: out = (I+C) x + d ; persistent per-batch blocks, occ 2 --------
#define NBLK_PER_B 37            // 8*37 = 296 blocks = 2 per SM, single wave
#define NTILES 256               // s-tiles of 64 per batch
#define SMEM_MAIN ((CH*CH + CH*64 + CH) * 4)
__global__ __launch_bounds__(256, 2) void k_main(const float* __restrict__ x,
                                                 float* __restrict__ out) {
    extern __shared__ float smem[];
    float* Cts = smem;                 // [128][128], Cts[c][o]
    float* xs  = smem + CH * CH;       // [128][64]
    float* d_s = xs + CH * 64;         // [128]

    int b = blockIdx.y;
    int t = threadIdx.x;

    // load Ct + d once per block
    {
        const float4* Ct4 = (const float4*)&g_Ct[b][0][0];
        float4* Cts4 = (float4*)Cts;
        for (int idx = t; idx < CH * CH / 4; idx += 256) Cts4[idx] = Ct4[idx];
        if (t < CH) d_s[t] = g_d[b][t];
    }

    int sx = t & 15, oy = t >> 4;      // 4 spatial cols, 16 oy -> 8 o-rows each
    const float* xb0 = x + (size_t)b * BSTRIDE;
    float* ob0 = out + (size_t)b * BSTRIDE;

    for (int st = blockIdx.x; st < NTILES; st += NBLK_PER_B) {
        const float* xb = xb0 + st * 64;
        __syncthreads();               // prev compute done reading xs; Ct visible
        #pragma unroll
        for (int w = 0; w < 8; ++w) {
            int idx = t + 256 * w;
            int row = idx >> 4, c4 = idx & 15;
            *(float4*)&xs[row * 64 + c4 * 4] = *(const float4*)(xb + row * SP + c4 * 4);
        }
        __syncthreads();

        u64 acc2[4][4];                // [o-pair][s]
        #pragma unroll
        for (int p = 0; p < 4; ++p)
            #pragma unroll
            for (int j = 0; j < 4; ++j) acc2[p][j] = 0ull;

        for (int c = 0; c < CH; ++c) {
            u64 c0 = *(const u64*)&Cts[c * CH + 8*oy + 0];   // native o-pairs
            u64 c1 = *(const u64*)&Cts[c * CH + 8*oy + 2];
            u64 c2 = *(const u64*)&Cts[c * CH + 8*oy + 4];
            u64 c3 = *(const u64*)&Cts[c * CH + 8*oy + 6];
            float4 xv = *(const float4*)&xs[c * 64 + 4*sx];
            u64 xx0 = pack2(xv.x, xv.x);
            u64 xx1 = pack2(xv.y, xv.y);
            u64 xx2 = pack2(xv.z, xv.z);
            u64 xx3 = pack2(xv.w, xv.w);
            fma2(acc2[0][0], c0, xx0); fma2(acc2[0][1], c0, xx1);
            fma2(acc2[0][2], c0, xx2); fma2(acc2[0][3], c0, xx3);
            fma2(acc2[1][0], c1, xx0); fma2(acc2[1][1], c1, xx1);
            fma2(acc2[1][2], c1, xx2); fma2(acc2[1][3], c1, xx3);
            fma2(acc2[2][0], c2, xx0); fma2(acc2[2][1], c2, xx1);
            fma2(acc2[2][2], c2, xx2); fma2(acc2[2][3], c2, xx3);
            fma2(acc2[3][0], c3, xx0); fma2(acc2[3][1], c3, xx1);
            fma2(acc2[3][2], c3, xx2); fma2(acc2[3][3], c3, xx3);
        }

        float* obt = ob0 + st * 64;
        #pragma unroll
        for (int p = 0; p < 4; ++p) {
            int o0 = 8*oy + 2*p;
            float2 v0 = unpack2(acc2[p][0]);
            float2 v1 = unpack2(acc2[p][1]);
            float2 v2 = unpack2(acc2[p][2]);
            float2 v3 = unpack2(acc2[p][3]);
            float d0 = d_s[o0], d1 = d_s[o0 + 1];
            float4 r0 = { v0.x + d0, v1.x + d0, v2.x + d0, v3.x + d0 };
            float4 r1 = { v0.y + d1, v1.y + d1, v2.y + d1, v3.y + d1 };
            *(float4*)(obt + o0 * SP + 4*sx) = r0;
            *(float4*)(obt + (o0 + 1) * SP + 4*sx) = r1;
        }
    }
}

extern "C" void kernel_launch(void* const* d_in, const int* in_sizes, int n_in,
                              void* d_out, int out_size) {
    const float* x    = (const float*)d_in[0];
    const float* gn_w = (const float*)d_in[1];
    const float* gn_b = (const float*)d_in[2];
    const float* w_in = (const float*)d_in[3];
    const float* b_in = (const float*)d_in[4];
    const float* w_out= (const float*)d_in[5];
    const float* b_out= (const float*)d_in[6];
    float* out = (float*)d_out;
    (void)in_sizes; (void)n_in; (void)out_size;

    cudaFuncSetAttribute(k_main,  cudaFuncAttributeMaxDynamicSharedMemorySize, SMEM_MAIN);
    cudaFuncSetAttribute(k_prep2, cudaFuncAttributeMaxDynamicSharedMemorySize, SMEM_P2);

    k_zero<<<512, 256>>>();
    dim3 gs(3, 16, NB);
    k_syrk<<<gs, 128>>>(x);
    k_prep1<<<NB, 128>>>(gn_w, gn_b, w_in, b_in);
    k_prep2<<<64, 512, SMEM_P2>>>(w_in, w_out);
    k_prep3<<<dim3(8, NB), 128>>>(w_in, b_out);
    k_main<<<dim3(NBLK_PER_B, NB), 256, SMEM_MAIN>>>(x, out);
}